// round 10
// baseline (speedup 1.0000x reference)
#include <cuda_runtime.h>
#include <cstdint>

#define TT     48000
#define NCH    512
#define NW     10                 // warps per block
#define NTHR   (NW * 32)          // 320
#define LCH    15                 // samples per lane per tile (odd -> conflict-free LDS)
#define WSLICE (32 * LCH)         // 480 samples per warp per tile
#define TILE   (NW * WSLICE)      // 4800
#define NTILE  (TT / TILE)        // 10 (exact)

#define FULLM 0xffffffffu

// 2x2 matrix multiply: O = A * B
#define MM(o00,o01,o10,o11, a00,a01,a10,a11, b00,b01,b10,b11) do { \
    float t00 = a00*b00 + a01*b10; \
    float t01 = a00*b01 + a01*b11; \
    float t10 = a10*b00 + a11*b10; \
    float t11 = a10*b01 + a11*b11; \
    o00=t00; o01=t01; o10=t10; o11=t11; } while(0)

__device__ __forceinline__ uint32_t s2u(const void* p) {
    return (uint32_t)__cvta_generic_to_shared(p);
}
__device__ __forceinline__ void cp_async16(uint32_t saddr, const void* gaddr) {
    asm volatile("cp.async.cg.shared.global [%0], [%1], 16;"
                 :: "r"(saddr), "l"(gaddr) : "memory");
}
__device__ __forceinline__ void cp_commit() {
    asm volatile("cp.async.commit_group;" ::: "memory");
}
template<int N> __device__ __forceinline__ void cp_wait() {
    asm volatile("cp.async.wait_group %0;" :: "n"(N) : "memory");
}

__global__ __launch_bounds__(NTHR, 5) void biquad_kernel(
    const float* __restrict__ x,
    const float* __restrict__ b0v, const float* __restrict__ b1v,
    const float* __restrict__ b2v, const float* __restrict__ a1v,
    const float* __restrict__ a2v, float* __restrict__ y)
{
    __shared__ __align__(16) float xs[NW * 2 * WSLICE];  // 38400 B
    __shared__ float sP[5 * 4];                   // P[k] = Q^(2^k)
    __shared__ float sT1[2][NW], sT2[2][NW];      // per-warp tile totals, parity-buffered

    const int ch   = blockIdx.x;
    const int tid  = threadIdx.x;
    const int lane = tid & 31;
    const int w    = tid >> 5;

    const float B0 = b0v[ch], B1 = b1v[ch], B2 = b2v[ch];
    const float A1 = a1v[ch], A2 = a2v[ch];
    const float nA1 = -A1, nA2 = -A2;

    // y-state transition: s[n] = (y[n], y[n-1]), s' = My s + (f,0),
    // My = [[-A1,-A2],[1,0]]. Q = My^LCH; P[k] = Q^(2^k); W = Q^32 = My^WSLICE.
    float p00[5], p01[5], p10[5], p11[5];
    {
        float m00 = nA1, m01 = nA2, m10 = 1.f, m11 = 0.f;
        float r00 = 1.f, r01 = 0.f, r10 = 0.f, r11 = 1.f;
        int e = LCH;
        while (e) {
            if (e & 1) { MM(r00,r01,r10,r11, r00,r01,r10,r11, m00,m01,m10,m11); }
            e >>= 1;
            if (e) { MM(m00,m01,m10,m11, m00,m01,m10,m11, m00,m01,m10,m11); }
        }
        p00[0] = r00; p01[0] = r01; p10[0] = r10; p11[0] = r11;
        #pragma unroll
        for (int k = 1; k < 5; ++k) {
            MM(p00[k],p01[k],p10[k],p11[k],
               p00[k-1],p01[k-1],p10[k-1],p11[k-1],
               p00[k-1],p01[k-1],p10[k-1],p11[k-1]);
        }
    }
    float W00, W01, W10, W11;  // Q^32 (hot: used 4*NW times per tile -> must stay in regs)
    MM(W00,W01,W10,W11, p00[4],p01[4],p10[4],p11[4], p00[4],p01[4],p10[4],p11[4]);

    // Qlane = Q^lane (cold: used 4 FMA per tile; spill is benign)
    float q00 = 1.f, q01 = 0.f, q10 = 0.f, q11 = 1.f;
    #pragma unroll
    for (int k = 0; k < 5; ++k) {
        if ((lane >> k) & 1) {
            MM(q00,q01,q10,q11, p00[k],p01[k],p10[k],p11[k], q00,q01,q10,q11);
        }
    }
    if (tid == 0) {
        #pragma unroll
        for (int k = 0; k < 5; ++k) {
            sP[k*4+0] = p00[k]; sP[k*4+1] = p01[k];
            sP[k*4+2] = p10[k]; sP[k*4+3] = p11[k];
        }
    }
    __syncthreads();

    // 32-bit addressing: single 64-bit base add, int offsets everywhere else.
    const float* __restrict__ xg = x + (uint32_t)(ch * TT);
    float* __restrict__       yg = y + (uint32_t)(ch * TT);
    const uint32_t sbuf0 = s2u(xs) + (uint32_t)(w * (2 * WSLICE * 4));
    float* const buf0 = xs + w * (2 * WSLICE);

    // Prefetch tile 0 (this warp's slice only)
    {
        const float* src = xg + w * WSLICE;
        #pragma unroll
        for (int i = lane; i < WSLICE / 4; i += 32)
            cp_async16(sbuf0 + i * 16, src + i * 4);
        cp_commit();
    }

    float carry1 = 0.f, carry2 = 0.f;   // (y[-1], y[-2]) entering tile; identical in all threads

    for (int t = 0; t < NTILE; ++t) {
        float* const buf = buf0 + (t & 1) * WSLICE;

        if (t + 1 < NTILE) {
            const float* src = xg + (t + 1) * TILE + w * WSLICE;
            const uint32_t dst = sbuf0 + (uint32_t)(((t + 1) & 1) * (WSLICE * 4));
            #pragma unroll
            for (int i = lane; i < WSLICE / 4; i += 32)
                cp_async16(dst + i * 16, src + i * 4);
            cp_commit();
            cp_wait<1>();
        } else {
            cp_wait<0>();
        }
        __syncwarp();

        float* const xc = buf + lane * LCH;

        // ---- x lookback ----
        float xm1, xm2;
        if (lane == 0) {
            const int g = t * TILE + w * WSLICE;
            xm1 = (g >= 1) ? __ldg(xg + g - 1) : 0.f;
            xm2 = (g >= 2) ? __ldg(xg + g - 2) : 0.f;
        } else {
            xm1 = xc[-1];
            xm2 = xc[-2];
        }

        // ---- pass 1: feedforward f into registers + zero-state recurrence ----
        float f[LCH];
        float y1 = 0.f, y2 = 0.f;
        #pragma unroll
        for (int k = 0; k < LCH; ++k) {
            float v = xc[k];
            float fk = fmaf(B0, v, fmaf(B1, xm1, B2 * xm2));
            f[k] = fk;
            float yn = fmaf(nA1, y1, fmaf(nA2, y2, fk));
            y2 = y1; y1 = yn; xm2 = xm1; xm1 = v;
        }

        // ---- warp inclusive affine scan of (y1,y2) chunk end states ----
        float E1 = y1, E2 = y2;
        #pragma unroll
        for (int k = 0; k < 5; ++k) {
            const int d = 1 << k;
            float u1 = __shfl_up_sync(FULLM, E1, d);
            float u2 = __shfl_up_sync(FULLM, E2, d);
            float a = sP[k*4+0], b = sP[k*4+1], c = sP[k*4+2], dd = sP[k*4+3];
            if (lane >= d) {
                E1 = fmaf(a, u1, fmaf(b, u2, E1));
                E2 = fmaf(c, u1, fmaf(dd, u2, E2));
            }
        }
        if (lane == 31) { sT1[t & 1][w] = E1; sT2[t & 1][w] = E2; }
        __syncthreads();   // one block barrier per tile

        // ---- cross-warp combine (redundant in every thread; 10 links) ----
        float c1 = carry1, c2 = carry2;
        float wc1 = 0.f, wc2 = 0.f;
        #pragma unroll
        for (int i = 0; i < NW; ++i) {
            if (i == w) { wc1 = c1; wc2 = c2; }
            float e1 = sT1[t & 1][i], e2 = sT2[t & 1][i];
            float n1 = fmaf(W00, c1, fmaf(W01, c2, e1));
            float n2 = fmaf(W10, c1, fmaf(W11, c2, e2));
            c1 = n1; c2 = n2;
        }
        carry1 = c1; carry2 = c2;

        // ---- true start state for this lane: S = Q^lane * wc + E_exclusive ----
        float Ex1 = __shfl_up_sync(FULLM, E1, 1);
        float Ex2 = __shfl_up_sync(FULLM, E2, 1);
        if (lane == 0) { Ex1 = 0.f; Ex2 = 0.f; }
        float ym1 = q00 * wc1 + q01 * wc2 + Ex1;   // y[start-1]
        float ym2 = q10 * wc1 + q11 * wc2 + Ex2;   // y[start-2]

        // ---- pass 2: y[n] = f[n] - a1 y[n-1] - a2 y[n-2]; STS into buffer ----
        #pragma unroll
        for (int k = 0; k < LCH; ++k) {
            float yn = fmaf(nA1, ym1, fmaf(nA2, ym2, f[k]));
            ym2 = ym1; ym1 = yn;
            xc[k] = yn;
        }
        __syncwarp();

        // ---- coalesced float4 store of this warp's slice ----
        float4* const yg4 = (float4*)(yg + t * TILE + w * WSLICE);
        const float4* const b4 = (const float4*)buf;
        #pragma unroll
        for (int i = lane; i < WSLICE / 4; i += 32)
            yg4[i] = b4[i];
        // next cp.async into this buffer: same lane rewrites exactly the float4
        // slots it just read (per-lane program order); other lanes' STS were
        // ordered by the __syncwarp above.
    }
}

extern "C" void kernel_launch(void* const* d_in, const int* in_sizes, int n_in,
                              void* d_out, int out_size)
{
    const float* x  = (const float*)d_in[0];
    const float* b0 = (const float*)d_in[1];
    const float* b1 = (const float*)d_in[2];
    const float* b2 = (const float*)d_in[3];
    const float* a1 = (const float*)d_in[4];
    const float* a2 = (const float*)d_in[5];
    float* yo = (float*)d_out;

    biquad_kernel<<<NCH, NTHR>>>(x, b0, b1, b2, a1, a2, yo);
}

// round 11
// speedup vs baseline: 1.1990x; 1.1990x over previous
#include <cuda_runtime.h>
#include <cstdint>

#define TT     48000
#define NCH    512
#define NW     10                 // warps per block
#define NTHR   (NW * 32)          // 320
#define LCH    15                 // samples per lane per tile (odd -> conflict-free LDS)
#define WSLICE (32 * LCH)         // 480 samples per warp per tile
#define WBYTES (WSLICE * 4)       // 1920 bytes per warp slice
#define TILE   (NW * WSLICE)      // 4800
#define NTILE  (TT / TILE)        // 10 (exact)

#define FULLM 0xffffffffu

// 2x2 matrix multiply: O = A * B
#define MM(o00,o01,o10,o11, a00,a01,a10,a11, b00,b01,b10,b11) do { \
    float t00 = a00*b00 + a01*b10; \
    float t01 = a00*b01 + a01*b11; \
    float t10 = a10*b00 + a11*b10; \
    float t11 = a10*b01 + a11*b11; \
    o00=t00; o01=t01; o10=t10; o11=t11; } while(0)

__device__ __forceinline__ uint32_t s2u(const void* p) {
    return (uint32_t)__cvta_generic_to_shared(p);
}
__device__ __forceinline__ void cp_async16(uint32_t saddr, const void* gaddr) {
    asm volatile("cp.async.cg.shared.global [%0], [%1], 16;"
                 :: "r"(saddr), "l"(gaddr) : "memory");
}
__device__ __forceinline__ void cp_commit() {
    asm volatile("cp.async.commit_group;" ::: "memory");
}
template<int N> __device__ __forceinline__ void cp_wait() {
    asm volatile("cp.async.wait_group %0;" :: "n"(N) : "memory");
}
// TMA bulk store: smem -> gmem, async engine, no warp LSU involvement
__device__ __forceinline__ void bulk_store(void* gaddr, uint32_t saddr, uint32_t bytes) {
    asm volatile("cp.async.bulk.global.shared::cta.bulk_group [%0], [%1], %2;"
                 :: "l"(gaddr), "r"(saddr), "r"(bytes) : "memory");
}
__device__ __forceinline__ void bulk_commit() {
    asm volatile("cp.async.bulk.commit_group;" ::: "memory");
}
template<int N> __device__ __forceinline__ void bulk_wait() {
    asm volatile("cp.async.bulk.wait_group %0;" :: "n"(N) : "memory");
}
__device__ __forceinline__ void fence_async() {
    asm volatile("fence.proxy.async.shared::cta;" ::: "memory");
}

__global__ __launch_bounds__(NTHR, 4) void biquad_kernel(
    const float* __restrict__ x,
    const float* __restrict__ b0v, const float* __restrict__ b1v,
    const float* __restrict__ b2v, const float* __restrict__ a1v,
    const float* __restrict__ a2v, float* __restrict__ y)
{
    __shared__ __align__(16) float xs[NW * 2 * WSLICE];  // 38400 B
    __shared__ float4 sP4[5];                  // P[k] = Q^(2^k), packed
    __shared__ float2 sT[2][NW];               // per-warp tile totals, parity-buffered

    const int ch   = blockIdx.x;
    const int tid  = threadIdx.x;
    const int lane = tid & 31;
    const int w    = tid >> 5;

    const float B0 = b0v[ch], B1 = b1v[ch], B2 = b2v[ch];
    const float A1 = a1v[ch], A2 = a2v[ch];
    const float nA1 = -A1, nA2 = -A2;

    // y-state transition: s[n] = (y[n], y[n-1]), s' = My s + (f,0),
    // My = [[-A1,-A2],[1,0]]. Q = My^LCH; P[k] = Q^(2^k); W = Q^32 = My^WSLICE.
    float p00[5], p01[5], p10[5], p11[5];
    {
        float m00 = nA1, m01 = nA2, m10 = 1.f, m11 = 0.f;
        float r00 = 1.f, r01 = 0.f, r10 = 0.f, r11 = 1.f;
        int e = LCH;
        while (e) {
            if (e & 1) { MM(r00,r01,r10,r11, r00,r01,r10,r11, m00,m01,m10,m11); }
            e >>= 1;
            if (e) { MM(m00,m01,m10,m11, m00,m01,m10,m11, m00,m01,m10,m11); }
        }
        p00[0] = r00; p01[0] = r01; p10[0] = r10; p11[0] = r11;
        #pragma unroll
        for (int k = 1; k < 5; ++k) {
            MM(p00[k],p01[k],p10[k],p11[k],
               p00[k-1],p01[k-1],p10[k-1],p11[k-1],
               p00[k-1],p01[k-1],p10[k-1],p11[k-1]);
        }
    }
    float W00, W01, W10, W11;  // Q^32 (hot)
    MM(W00,W01,W10,W11, p00[4],p01[4],p10[4],p11[4], p00[4],p01[4],p10[4],p11[4]);

    // Qlane = Q^lane
    float q00 = 1.f, q01 = 0.f, q10 = 0.f, q11 = 1.f;
    #pragma unroll
    for (int k = 0; k < 5; ++k) {
        if ((lane >> k) & 1) {
            MM(q00,q01,q10,q11, p00[k],p01[k],p10[k],p11[k], q00,q01,q10,q11);
        }
    }
    if (tid == 0) {
        #pragma unroll
        for (int k = 0; k < 5; ++k)
            sP4[k] = make_float4(p00[k], p01[k], p10[k], p11[k]);
    }
    __syncthreads();

    const float* __restrict__ xg = x + (uint32_t)(ch * TT);
    float* __restrict__       yg = y + (uint32_t)(ch * TT);
    float* const buf0 = xs + w * (2 * WSLICE);
    const uint32_t sbuf0 = s2u(xs) + (uint32_t)(w * (2 * WBYTES));

    // Prefetch tile 0 (this warp's slice only)
    {
        const float* src = xg + w * WSLICE;
        #pragma unroll
        for (int i = lane; i < WSLICE / 4; i += 32)
            cp_async16(sbuf0 + i * 16, src + i * 4);
        cp_commit();
    }

    // Lane-0 lookback registers for tile 0 (global x[-1], x[-2] of own chunk)
    float lb1 = 0.f, lb2 = 0.f;
    if (lane == 0 && w > 0) {
        lb1 = __ldg(xg + w * WSLICE - 1);
        lb2 = __ldg(xg + w * WSLICE - 2);
    }

    float carry1 = 0.f, carry2 = 0.f;   // (y[-1], y[-2]) entering tile; identical in all threads

    for (int t = 0; t < NTILE; ++t) {
        float* const buf = buf0 + (t & 1) * WSLICE;

        cp_wait<0>();     // this tile's staging (issued mid-previous-tile) complete
        __syncwarp();     // make all lanes' cp.async results visible warp-wide

        float* const xc = buf + lane * LCH;

        // ---- x lookback (lane 0: prefetched regs; others: own-warp smem) ----
        float xm1, xm2;
        if (lane == 0) { xm1 = lb1; xm2 = lb2; }
        else           { xm1 = xc[-1]; xm2 = xc[-2]; }

        // ---- pass 1: feedforward f into registers + zero-state recurrence ----
        float f[LCH];
        float y1 = 0.f, y2 = 0.f;
        #pragma unroll
        for (int k = 0; k < LCH; ++k) {
            float v = xc[k];
            float fk = fmaf(B0, v, fmaf(B1, xm1, B2 * xm2));
            f[k] = fk;
            float yn = fmaf(nA1, y1, fmaf(nA2, y2, fk));
            y2 = y1; y1 = yn; xm2 = xm1; xm1 = v;
        }

        // ---- warp inclusive affine scan of (y1,y2) chunk end states ----
        float E1 = y1, E2 = y2;
        #pragma unroll
        for (int k = 0; k < 5; ++k) {
            const int d = 1 << k;
            float u1 = __shfl_up_sync(FULLM, E1, d);
            float u2 = __shfl_up_sync(FULLM, E2, d);
            float4 P = sP4[k];
            if (lane >= d) {
                E1 = fmaf(P.x, u1, fmaf(P.y, u2, E1));
                E2 = fmaf(P.z, u1, fmaf(P.w, u2, E2));
            }
        }
        if (lane == 31) sT[t & 1][w] = make_float2(E1, E2);
        __syncthreads();   // one block barrier per tile

        // ---- stage tile t+1 (after barrier: prev bulk store had time to drain) ----
        if (t + 1 < NTILE) {
            if (lane == 0) bulk_wait<0>();   // buffer (t+1)&1's old y fully read out
            __syncwarp();
            const float* src = xg + (t + 1) * TILE + w * WSLICE;
            const uint32_t dst = sbuf0 + (uint32_t)(((t + 1) & 1) * WBYTES);
            #pragma unroll
            for (int i = lane; i < WSLICE / 4; i += 32)
                cp_async16(dst + i * 16, src + i * 4);
            cp_commit();
            if (lane == 0) {   // lookback prefetch for tile t+1 (g >= 2 always here)
                const int g = (t + 1) * TILE + w * WSLICE;
                lb1 = __ldg(xg + g - 1);
                lb2 = __ldg(xg + g - 2);
            }
        }

        // ---- cross-warp combine (redundant in every thread; 10 links) ----
        float c1 = carry1, c2 = carry2;
        float wc1 = 0.f, wc2 = 0.f;
        #pragma unroll
        for (int i = 0; i < NW; ++i) {
            if (i == w) { wc1 = c1; wc2 = c2; }
            float2 e = sT[t & 1][i];
            float n1 = fmaf(W00, c1, fmaf(W01, c2, e.x));
            float n2 = fmaf(W10, c1, fmaf(W11, c2, e.y));
            c1 = n1; c2 = n2;
        }
        carry1 = c1; carry2 = c2;

        // ---- true start state for this lane: S = Q^lane * wc + E_exclusive ----
        float Ex1 = __shfl_up_sync(FULLM, E1, 1);
        float Ex2 = __shfl_up_sync(FULLM, E2, 1);
        if (lane == 0) { Ex1 = 0.f; Ex2 = 0.f; }
        float ym1 = q00 * wc1 + q01 * wc2 + Ex1;   // y[start-1]
        float ym2 = q10 * wc1 + q11 * wc2 + Ex2;   // y[start-2]

        // ---- pass 2: y[n] = f[n] - a1 y[n-1] - a2 y[n-2]; STS into buffer ----
        #pragma unroll
        for (int k = 0; k < LCH; ++k) {
            float yn = fmaf(nA1, ym1, fmaf(nA2, ym2, f[k]));
            ym2 = ym1; ym1 = yn;
            xc[k] = yn;
        }
        __syncwarp();      // all lanes' STS done before the async-proxy read

        // ---- TMA bulk store of this warp's slice (lane 0 only) ----
        if (lane == 0) {
            fence_async();  // order generic-proxy STS before async-proxy read
            bulk_store(yg + t * TILE + w * WSLICE, s2u(buf), WBYTES);
            bulk_commit();
        }
    }
    if (lane == 0) bulk_wait<0>();   // drain final store before kernel exit
}

extern "C" void kernel_launch(void* const* d_in, const int* in_sizes, int n_in,
                              void* d_out, int out_size)
{
    const float* x  = (const float*)d_in[0];
    const float* b0 = (const float*)d_in[1];
    const float* b1 = (const float*)d_in[2];
    const float* b2 = (const float*)d_in[3];
    const float* a1 = (const float*)d_in[4];
    const float* a2 = (const float*)d_in[5];
    float* yo = (float*)d_out;

    biquad_kernel<<<NCH, NTHR>>>(x, b0, b1, b2, a1, a2, yo);
}

// round 14
// speedup vs baseline: 1.2000x; 1.0009x over previous
#include <cuda_runtime.h>
#include <cstdint>

#define TT     48000
#define NCH    512
#define NW     10                 // warps per block
#define NTHR   (NW * 32)          // 320
#define LCH    15                 // samples per lane per tile (odd -> conflict-free LDS)
#define WSLICE (32 * LCH)         // 480 samples per warp per tile
#define WBYTES (WSLICE * 4)       // 1920 bytes per warp slice
#define TILE   (NW * WSLICE)      // 4800
#define NTILE  (TT / TILE)        // 10 (exact)

#define FULLM 0xffffffffu

// 2x2 matrix multiply: O = A * B
#define MM(o00,o01,o10,o11, a00,a01,a10,a11, b00,b01,b10,b11) do { \
    float t00 = a00*b00 + a01*b10; \
    float t01 = a00*b01 + a01*b11; \
    float t10 = a10*b00 + a11*b10; \
    float t11 = a10*b01 + a11*b11; \
    o00=t00; o01=t01; o10=t10; o11=t11; } while(0)

__device__ __forceinline__ uint32_t s2u(const void* p) {
    return (uint32_t)__cvta_generic_to_shared(p);
}
__device__ __forceinline__ void cp_async16(uint32_t saddr, const void* gaddr) {
    asm volatile("cp.async.cg.shared.global [%0], [%1], 16;"
                 :: "r"(saddr), "l"(gaddr) : "memory");
}
__device__ __forceinline__ void cp_commit() {
    asm volatile("cp.async.commit_group;" ::: "memory");
}
template<int N> __device__ __forceinline__ void cp_wait() {
    asm volatile("cp.async.wait_group %0;" :: "n"(N) : "memory");
}
// TMA bulk store: smem -> gmem, async engine
__device__ __forceinline__ void bulk_store(void* gaddr, uint32_t saddr, uint32_t bytes) {
    asm volatile("cp.async.bulk.global.shared::cta.bulk_group [%0], [%1], %2;"
                 :: "l"(gaddr), "r"(saddr), "r"(bytes) : "memory");
}
__device__ __forceinline__ void bulk_commit() {
    asm volatile("cp.async.bulk.commit_group;" ::: "memory");
}
template<int N> __device__ __forceinline__ void bulk_wait() {
    asm volatile("cp.async.bulk.wait_group %0;" :: "n"(N) : "memory");
}
__device__ __forceinline__ void fence_async() {
    asm volatile("fence.proxy.async.shared::cta;" ::: "memory");
}

__global__ __launch_bounds__(NTHR, 4) void biquad_kernel(
    const float* __restrict__ x,
    const float* __restrict__ b0v, const float* __restrict__ b1v,
    const float* __restrict__ b2v, const float* __restrict__ a1v,
    const float* __restrict__ a2v, float* __restrict__ y)
{
    __shared__ __align__(16) float xs[NW * 2 * WSLICE];  // 38400 B
    __shared__ float4 sP4[5];        // P[k] = Q^(2^k)  (intra-warp scan matrices)
    __shared__ float4 sV4[4];        // V[k] = W^(2^k)  (totals-scan matrices)
    __shared__ float4 sWp4[NW];      // W^w per warp
    __shared__ float4 sW10;          // W^10 (full-tile transition)
    __shared__ float2 sT[2][NW];     // per-warp tile totals, parity-buffered

    const int ch   = blockIdx.x;
    const int tid  = threadIdx.x;
    const int lane = tid & 31;
    const int w    = tid >> 5;

    const float B0 = b0v[ch], B1 = b1v[ch], B2 = b2v[ch];
    const float A1 = a1v[ch], A2 = a2v[ch];
    const float nA1 = -A1, nA2 = -A2;

    // y-state transition: s[n] = (y[n], y[n-1]), s' = My s + (f,0),
    // My = [[-A1,-A2],[1,0]]. Q = My^LCH; P[k] = Q^(2^k); W = Q^32 = My^WSLICE.
    float p00[5], p01[5], p10[5], p11[5];
    {
        float m00 = nA1, m01 = nA2, m10 = 1.f, m11 = 0.f;
        float r00 = 1.f, r01 = 0.f, r10 = 0.f, r11 = 1.f;
        int e = LCH;
        while (e) {
            if (e & 1) { MM(r00,r01,r10,r11, r00,r01,r10,r11, m00,m01,m10,m11); }
            e >>= 1;
            if (e) { MM(m00,m01,m10,m11, m00,m01,m10,m11, m00,m01,m10,m11); }
        }
        p00[0] = r00; p01[0] = r01; p10[0] = r10; p11[0] = r11;
        #pragma unroll
        for (int k = 1; k < 5; ++k) {
            MM(p00[k],p01[k],p10[k],p11[k],
               p00[k-1],p01[k-1],p10[k-1],p11[k-1],
               p00[k-1],p01[k-1],p10[k-1],p11[k-1]);
        }
    }

    // Qlane = Q^lane
    float q00 = 1.f, q01 = 0.f, q10 = 0.f, q11 = 1.f;
    #pragma unroll
    for (int k = 0; k < 5; ++k) {
        if ((lane >> k) & 1) {
            MM(q00,q01,q10,q11, p00[k],p01[k],p10[k],p11[k], q00,q01,q10,q11);
        }
    }

    if (tid == 0) {
        #pragma unroll
        for (int k = 0; k < 5; ++k)
            sP4[k] = make_float4(p00[k], p01[k], p10[k], p11[k]);
        // W = Q^32; V[k] = W^(2^k); W^w for w=0..9; W^10
        float W00, W01, W10_, W11;
        MM(W00,W01,W10_,W11, p00[4],p01[4],p10[4],p11[4], p00[4],p01[4],p10[4],p11[4]);
        float v00 = W00, v01 = W01, v10 = W10_, v11 = W11;
        #pragma unroll
        for (int k = 0; k < 4; ++k) {
            sV4[k] = make_float4(v00, v01, v10, v11);
            if (k < 3) { MM(v00,v01,v10,v11, v00,v01,v10,v11, v00,v01,v10,v11); }
        }
        float c00 = 1.f, c01 = 0.f, c10 = 0.f, c11 = 1.f;   // W^0
        #pragma unroll
        for (int i = 0; i < NW; ++i) {
            sWp4[i] = make_float4(c00, c01, c10, c11);
            MM(c00,c01,c10,c11, W00,W01,W10_,W11, c00,c01,c10,c11);
        }
        sW10 = make_float4(c00, c01, c10, c11);             // W^10
    }
    __syncthreads();

    const float* __restrict__ xg = x + (uint32_t)(ch * TT);
    float* __restrict__       yg = y + (uint32_t)(ch * TT);
    float* const buf0 = xs + w * (2 * WSLICE);
    const uint32_t sbuf0 = s2u(xs) + (uint32_t)(w * (2 * WBYTES));

    // Prefetch tile 0 (this warp's slice only)
    {
        const float* src = xg + w * WSLICE;
        #pragma unroll
        for (int i = lane; i < WSLICE / 4; i += 32)
            cp_async16(sbuf0 + i * 16, src + i * 4);
        cp_commit();
    }

    // Lane-0 lookback registers for tile 0
    float lb1 = 0.f, lb2 = 0.f;
    if (lane == 0 && w > 0) {
        lb1 = __ldg(xg + w * WSLICE - 1);
        lb2 = __ldg(xg + w * WSLICE - 2);
    }

    float carry1 = 0.f, carry2 = 0.f;   // (y[-1], y[-2]) entering tile; identical in all threads

    for (int t = 0; t < NTILE; ++t) {
        float* const buf = buf0 + (t & 1) * WSLICE;

        cp_wait<0>();     // this tile's staging complete
        __syncwarp();

        float* const xc = buf + lane * LCH;

        // ---- x lookback (lane 0: prefetched regs; others: own-warp smem) ----
        float xm1, xm2;
        if (lane == 0) { xm1 = lb1; xm2 = lb2; }
        else           { xm1 = xc[-1]; xm2 = xc[-2]; }

        // ---- pass 1: feedforward f into registers + zero-state recurrence ----
        float f[LCH];
        float y1 = 0.f, y2 = 0.f;
        #pragma unroll
        for (int k = 0; k < LCH; ++k) {
            float v = xc[k];
            float fk = fmaf(B0, v, fmaf(B1, xm1, B2 * xm2));
            f[k] = fk;
            float yn = fmaf(nA1, y1, fmaf(nA2, y2, fk));
            y2 = y1; y1 = yn; xm2 = xm1; xm1 = v;
        }

        // ---- warp inclusive affine scan of (y1,y2) chunk end states ----
        float E1 = y1, E2 = y2;
        #pragma unroll
        for (int k = 0; k < 5; ++k) {
            const int d = 1 << k;
            float u1 = __shfl_up_sync(FULLM, E1, d);
            float u2 = __shfl_up_sync(FULLM, E2, d);
            float4 P = sP4[k];
            if (lane >= d) {
                E1 = fmaf(P.x, u1, fmaf(P.y, u2, E1));
                E2 = fmaf(P.z, u1, fmaf(P.w, u2, E2));
            }
        }
        if (lane == 31) sT[t & 1][w] = make_float2(E1, E2);
        __syncthreads();   // one block barrier per tile

        // ---- stage tile t+1 (after barrier: prev bulk store had time to drain) ----
        if (t + 1 < NTILE) {
            if (lane == 0) bulk_wait<0>();   // buffer (t+1)&1's old y fully read out
            __syncwarp();
            const float* src = xg + (t + 1) * TILE + w * WSLICE;
            const uint32_t dst = sbuf0 + (uint32_t)(((t + 1) & 1) * WBYTES);
            #pragma unroll
            for (int i = lane; i < WSLICE / 4; i += 32)
                cp_async16(dst + i * 16, src + i * 4);
            cp_commit();
            if (lane == 0) {
                const int g = (t + 1) * TILE + w * WSLICE;
                lb1 = __ldg(xg + g - 1);
                lb2 = __ldg(xg + g - 2);
            }
        }

        // ---- lane-parallel scan of the 10 warp totals (redundant per warp) ----
        // G_i = sum_{j<=i} W^(i-j) e_j  via Kogge-Stone with V[k] = W^(2^k)
        float G1 = 0.f, G2 = 0.f;
        if (lane < NW) {
            float2 e = sT[t & 1][lane];
            G1 = e.x; G2 = e.y;
        }
        #pragma unroll
        for (int k = 0; k < 4; ++k) {
            const int d = 1 << k;
            float u1 = __shfl_up_sync(FULLM, G1, d);
            float u2 = __shfl_up_sync(FULLM, G2, d);
            float4 V = sV4[k];
            if (lane >= d) {
                G1 = fmaf(V.x, u1, fmaf(V.y, u2, G1));
                G2 = fmaf(V.z, u1, fmaf(V.w, u2, G2));
            }
        }
        // exclusive prefix for own warp: F_{w-1} (zero for w==0); total: F_9
        const int src = (w > 0) ? (w - 1) : 0;
        float Fm1 = __shfl_sync(FULLM, G1, src);
        float Fm2 = __shfl_sync(FULLM, G2, src);
        if (w == 0) { Fm1 = 0.f; Fm2 = 0.f; }
        float Ft1 = __shfl_sync(FULLM, G1, NW - 1);
        float Ft2 = __shfl_sync(FULLM, G2, NW - 1);

        float4 Wp = sWp4[w];      // W^w (broadcast LDS)
        float wc1 = fmaf(Wp.x, carry1, fmaf(Wp.y, carry2, Fm1));
        float wc2 = fmaf(Wp.z, carry1, fmaf(Wp.w, carry2, Fm2));
        float4 WT = sW10;         // W^10
        float nc1 = fmaf(WT.x, carry1, fmaf(WT.y, carry2, Ft1));
        float nc2 = fmaf(WT.z, carry1, fmaf(WT.w, carry2, Ft2));
        carry1 = nc1; carry2 = nc2;

        // ---- true start state for this lane: S = Q^lane * wc + E_exclusive ----
        float Ex1 = __shfl_up_sync(FULLM, E1, 1);
        float Ex2 = __shfl_up_sync(FULLM, E2, 1);
        if (lane == 0) { Ex1 = 0.f; Ex2 = 0.f; }
        float ym1 = q00 * wc1 + q01 * wc2 + Ex1;   // y[start-1]
        float ym2 = q10 * wc1 + q11 * wc2 + Ex2;   // y[start-2]

        // ---- pass 2: y[n] = f[n] - a1 y[n-1] - a2 y[n-2]; STS into buffer ----
        #pragma unroll
        for (int k = 0; k < LCH; ++k) {
            float yn = fmaf(nA1, ym1, fmaf(nA2, ym2, f[k]));
            ym2 = ym1; ym1 = yn;
            xc[k] = yn;
        }
        __syncwarp();      // all lanes' STS done before async-proxy read

        // ---- TMA bulk store of this warp's slice (lane 0 only) ----
        if (lane == 0) {
            fence_async();
            bulk_store(yg + t * TILE + w * WSLICE, s2u(buf), WBYTES);
            bulk_commit();
        }
    }
    if (lane == 0) bulk_wait<0>();   // drain final store before kernel exit
}

extern "C" void kernel_launch(void* const* d_in, const int* in_sizes, int n_in,
                              void* d_out, int out_size)
{
    const float* x  = (const float*)d_in[0];
    const float* b0 = (const float*)d_in[1];
    const float* b1 = (const float*)d_in[2];
    const float* b2 = (const float*)d_in[3];
    const float* a1 = (const float*)d_in[4];
    const float* a2 = (const float*)d_in[5];
    float* yo = (float*)d_out;

    biquad_kernel<<<NCH, NTHR>>>(x, b0, b1, b2, a1, a2, yo);
}